// round 3
// baseline (speedup 1.0000x reference)
#include <cuda_runtime.h>
#include <cstdint>

// ---------------------------------------------------------------------------
// Smolgen pipeline on GB300 (sm_103a), round 0: TF32 mma.sync GEMMs.
//   A: compressed = x @ W_tc^T            (65536 x 32,  K=1024)
//   B: g_raw = flat @ W_gc^T              (1024 x 256,  K=2048)
//      rmsnorm: g = (g_raw+b)/rms * scale
//   C: hr = g @ W_heads^T                 (1024 x 4096, K=256)
//   D: out = hr(16384x256) @ W_logit^T    (16384 x 4096, K=256)
// ---------------------------------------------------------------------------

// Scratch (allocation-free rule: __device__ globals)
__device__ float g_flat[1024 * 2048];   // stage A output
__device__ float g_graw[1024 * 256];    // stage B output (pre-norm)
__device__ float g_g[1024 * 256];       // post-RMSNorm
__device__ float g_hr[1024 * 4096];     // stage C output

__device__ __forceinline__ float to_tf32(float x) {
    float y;
    asm("cvt.rna.tf32.f32 %0, %1;" : "=f"(y) : "f"(x));
    return y;
}

__device__ __forceinline__ void mma_tf32(float* d, const uint32_t* a, const uint32_t* b) {
    asm volatile(
        "mma.sync.aligned.m16n8k8.row.col.f32.tf32.tf32.f32 "
        "{%0,%1,%2,%3},{%4,%5,%6,%7},{%8,%9},{%0,%1,%2,%3};"
        : "+f"(d[0]), "+f"(d[1]), "+f"(d[2]), "+f"(d[3])
        : "r"(a[0]), "r"(a[1]), "r"(a[2]), "r"(a[3]), "r"(b[0]), "r"(b[1]));
}

// C[M,N] = A[M,K] @ B[N,K]^T, all row-major fp32. M%BM==0, N%BN==0, K%BK==0.
template <int BM, int BN, int BK, int WARPS_M, int WARPS_N, int WM_ITER, int WN_ITER>
__global__ void __launch_bounds__(WARPS_M* WARPS_N * 32)
    gemm_tf32(const float* __restrict__ A, const float* __restrict__ B,
              float* __restrict__ C, int M, int N, int K) {
    static_assert(BM == WARPS_M * WM_ITER * 16, "BM mismatch");
    static_assert(BN == WARPS_N * WN_ITER * 8, "BN mismatch");
    constexpr int THREADS = WARPS_M * WARPS_N * 32;
    constexpr int PAD = 4;  // stride 36 floats -> conflict-free fragment reads

    __shared__ float As[BM][BK + PAD];
    __shared__ float Bs[BN][BK + PAD];

    const int tid = threadIdx.x;
    const int warp = tid >> 5;
    const int lane = tid & 31;
    const int gid = lane >> 2;   // group-of-4 id (0..7)
    const int tig = lane & 3;    // thread-in-group (0..3)
    const int warp_m = warp / WARPS_N;
    const int warp_n = warp % WARPS_N;
    const int wm0 = warp_m * (WM_ITER * 16);
    const int wn0 = warp_n * (WN_ITER * 8);
    const long brow = (long)blockIdx.y * BM;
    const long bcol = (long)blockIdx.x * BN;

    float acc[WM_ITER][WN_ITER][4];
#pragma unroll
    for (int i = 0; i < WM_ITER; i++)
#pragma unroll
        for (int j = 0; j < WN_ITER; j++)
#pragma unroll
            for (int t = 0; t < 4; t++) acc[i][j][t] = 0.0f;

    constexpr int A_LD = (BM * BK / 4) / THREADS;
    constexpr int B_LD = (BN * BK / 4) / THREADS;
    static_assert(A_LD * THREADS * 4 == BM * BK, "A load mismatch");
    static_assert(B_LD * THREADS * 4 == BN * BK, "B load mismatch");

    for (int k0 = 0; k0 < K; k0 += BK) {
#pragma unroll
        for (int i = 0; i < A_LD; i++) {
            int idx = tid + i * THREADS;
            int r = idx / (BK / 4);
            int c4 = (idx % (BK / 4)) * 4;
            float4 v = *reinterpret_cast<const float4*>(A + (brow + r) * K + k0 + c4);
            As[r][c4 + 0] = to_tf32(v.x);
            As[r][c4 + 1] = to_tf32(v.y);
            As[r][c4 + 2] = to_tf32(v.z);
            As[r][c4 + 3] = to_tf32(v.w);
        }
#pragma unroll
        for (int i = 0; i < B_LD; i++) {
            int idx = tid + i * THREADS;
            int r = idx / (BK / 4);
            int c4 = (idx % (BK / 4)) * 4;
            float4 v = *reinterpret_cast<const float4*>(B + (bcol + r) * K + k0 + c4);
            Bs[r][c4 + 0] = to_tf32(v.x);
            Bs[r][c4 + 1] = to_tf32(v.y);
            Bs[r][c4 + 2] = to_tf32(v.z);
            Bs[r][c4 + 3] = to_tf32(v.w);
        }
        __syncthreads();

#pragma unroll
        for (int ks = 0; ks < BK / 8; ks++) {
            uint32_t af[WM_ITER][4];
            uint32_t bf[WN_ITER][2];
#pragma unroll
            for (int i = 0; i < WM_ITER; i++) {
                int r = wm0 + i * 16;
                af[i][0] = __float_as_uint(As[r + gid][ks * 8 + tig]);
                af[i][1] = __float_as_uint(As[r + gid + 8][ks * 8 + tig]);
                af[i][2] = __float_as_uint(As[r + gid][ks * 8 + tig + 4]);
                af[i][3] = __float_as_uint(As[r + gid + 8][ks * 8 + tig + 4]);
            }
#pragma unroll
            for (int j = 0; j < WN_ITER; j++) {
                int c = wn0 + j * 8;
                bf[j][0] = __float_as_uint(Bs[c + gid][ks * 8 + tig]);
                bf[j][1] = __float_as_uint(Bs[c + gid][ks * 8 + tig + 4]);
            }
#pragma unroll
            for (int i = 0; i < WM_ITER; i++)
#pragma unroll
                for (int j = 0; j < WN_ITER; j++) mma_tf32(acc[i][j], af[i], bf[j]);
        }
        __syncthreads();
    }

    // Epilogue: c0,c1 adjacent cols at (gid, 2*tig); c2,c3 at row+8.
#pragma unroll
    for (int i = 0; i < WM_ITER; i++) {
#pragma unroll
        for (int j = 0; j < WN_ITER; j++) {
            long r = brow + wm0 + i * 16 + gid;
            long c = bcol + wn0 + j * 8 + tig * 2;
            *reinterpret_cast<float2*>(C + r * N + c) =
                make_float2(acc[i][j][0], acc[i][j][1]);
            *reinterpret_cast<float2*>(C + (r + 8) * N + c) =
                make_float2(acc[i][j][2], acc[i][j][3]);
        }
    }
}

// One block per batch row: g = (g_raw + bias) * rsqrt(mean(sq)+eps) * scale
__global__ void rmsnorm_kernel(const float* __restrict__ gin,
                               const float* __restrict__ bias,
                               const float* __restrict__ scale,
                               float* __restrict__ gout) {
    const int b = blockIdx.x;
    const int h = threadIdx.x;  // 256 threads
    float v = gin[b * 256 + h] + bias[h];
    float s = v * v;
#pragma unroll
    for (int o = 16; o > 0; o >>= 1) s += __shfl_xor_sync(0xFFFFFFFFu, s, o);
    __shared__ float ws[8];
    if ((h & 31) == 0) ws[h >> 5] = s;
    __syncthreads();
    float tot = 0.0f;
#pragma unroll
    for (int w = 0; w < 8; w++) tot += ws[w];
    float inv = rsqrtf(tot * (1.0f / 256.0f) + 1e-6f);
    gout[b * 256 + h] = v * inv * scale[h];
}

extern "C" void kernel_launch(void* const* d_in, const int* in_sizes, int n_in,
                              void* d_out, int out_size) {
    const float* x         = (const float*)d_in[0];  // (1024, 64, 1024)
    const float* W_tc      = (const float*)d_in[1];  // (32, 1024)
    const float* W_gc      = (const float*)d_in[2];  // (256, 2048)
    const float* b_gc      = (const float*)d_in[3];  // (256,)
    const float* rms_scale = (const float*)d_in[4];  // (256,)
    const float* W_heads   = (const float*)d_in[5];  // (16, 256, 256) -> (4096, 256)
    const float* W_logit   = (const float*)d_in[6];  // (4096, 256)
    float* out = (float*)d_out;                      // (1024, 16, 64, 64)

    float *flat, *graw, *gg, *hr;
    cudaGetSymbolAddress((void**)&flat, g_flat);
    cudaGetSymbolAddress((void**)&graw, g_graw);
    cudaGetSymbolAddress((void**)&gg, g_g);
    cudaGetSymbolAddress((void**)&hr, g_hr);

    // Stage A: M=65536, N=32, K=1024.  BM=128, BN=32.
    gemm_tf32<128, 32, 32, 8, 1, 1, 4>
        <<<dim3(1, 512), 256>>>(x, W_tc, flat, 65536, 32, 1024);

    // Stage B: M=1024, N=256, K=2048.  BM=128, BN=64.
    gemm_tf32<128, 64, 32, 2, 4, 4, 2>
        <<<dim3(4, 8), 256>>>(flat, W_gc, graw, 1024, 256, 2048);

    // RMSNorm (with bias add)
    rmsnorm_kernel<<<1024, 256>>>(graw, b_gc, rms_scale, gg);

    // Stage C: M=1024, N=4096, K=256.  BM=128, BN=128.
    gemm_tf32<128, 128, 32, 2, 4, 4, 4>
        <<<dim3(32, 8), 256>>>(gg, W_heads, hr, 1024, 4096, 256);

    // Stage D: M=16384, N=4096, K=256.  Output written directly, row m=b*16+n.
    gemm_tf32<128, 128, 32, 2, 4, 4, 4>
        <<<dim3(32, 128), 256>>>(hr, W_logit, out, 16384, 4096, 256);
}

// round 4
// speedup vs baseline: 1.2757x; 1.2757x over previous
#include <cuda_runtime.h>
#include <cstdint>

// ---------------------------------------------------------------------------
// Smolgen pipeline on GB300 (sm_103a), round 3: cp.async 3-stage pipelined
// TF32 mma.sync GEMMs.
//   A: compressed = x @ W_tc^T            (65536 x 32,  K=1024)
//   B: g_raw = flat @ W_gc^T              (1024 x 256,  K=2048)
//      rmsnorm: g = (g_raw+b)/rms * scale
//   C: hr = g @ W_heads^T                 (1024 x 4096, K=256)
//   D: out = hr(16384x256) @ W_logit^T    (16384 x 4096, K=256)
// ---------------------------------------------------------------------------

__device__ float g_flat[1024 * 2048];
__device__ float g_graw[1024 * 256];
__device__ float g_g[1024 * 256];
__device__ float g_hr[1024 * 4096];

__device__ __forceinline__ uint32_t as_tf32(float x) {
    float y;
    asm("cvt.rna.tf32.f32 %0, %1;" : "=f"(y) : "f"(x));
    return __float_as_uint(y);
}

__device__ __forceinline__ void mma_tf32(float* d, const uint32_t* a, const uint32_t* b) {
    asm volatile(
        "mma.sync.aligned.m16n8k8.row.col.f32.tf32.tf32.f32 "
        "{%0,%1,%2,%3},{%4,%5,%6,%7},{%8,%9},{%0,%1,%2,%3};"
        : "+f"(d[0]), "+f"(d[1]), "+f"(d[2]), "+f"(d[3])
        : "r"(a[0]), "r"(a[1]), "r"(a[2]), "r"(a[3]), "r"(b[0]), "r"(b[1]));
}

__device__ __forceinline__ void cp16(uint32_t saddr, const float* gptr) {
    asm volatile("cp.async.cg.shared.global [%0], [%1], 16;" ::"r"(saddr), "l"(gptr));
}
__device__ __forceinline__ void cp_commit() {
    asm volatile("cp.async.commit_group;");
}

// C[M,N] = A[M,K] @ B[N,K]^T, all row-major fp32. Dims divide tiles exactly.
template <int BM, int BN, int BK, int WARPS_M, int WARPS_N, int WM_ITER, int WN_ITER,
          int STAGES>
__global__ void __launch_bounds__(WARPS_M* WARPS_N * 32)
    gemm_tf32_pipe(const float* __restrict__ A, const float* __restrict__ B,
                   float* __restrict__ C, int M, int N, int K) {
    static_assert(BM == WARPS_M * WM_ITER * 16, "BM mismatch");
    static_assert(BN == WARPS_N * WN_ITER * 8, "BN mismatch");
    constexpr int THREADS = WARPS_M * WARPS_N * 32;
    constexpr int PAD = 4;  // row stride 36 floats -> conflict-free fragment LDS
    constexpr int LDR = BK + PAD;
    constexpr int ASZ = BM * LDR;
    constexpr int BSZ = BN * LDR;
    constexpr int SSZ = ASZ + BSZ;

    extern __shared__ float smem[];

    const int tid = threadIdx.x;
    const int warp = tid >> 5;
    const int lane = tid & 31;
    const int gid = lane >> 2;
    const int tig = lane & 3;
    const int warp_m = warp / WARPS_N;
    const int warp_n = warp % WARPS_N;
    const int wm0 = warp_m * (WM_ITER * 16);
    const int wn0 = warp_n * (WN_ITER * 8);
    const long brow = (long)blockIdx.y * BM;
    const long bcol = (long)blockIdx.x * BN;

    constexpr int A_LD = (BM * BK / 4) / THREADS;
    constexpr int B_LD = (BN * BK / 4) / THREADS;
    static_assert(A_LD * THREADS * 4 == BM * BK, "A load mismatch");
    static_assert(B_LD * THREADS * 4 == BN * BK, "B load mismatch");
    static_assert(B_LD >= 1, "B load mismatch");

    const int NK = K / BK;

    // Issue one k-tile's cp.async loads into stage kt % STAGES.
    auto issue_tile = [&](int kt) {
        const int st = kt % STAGES;
        float* As = smem + st * SSZ;
        float* Bs = As + ASZ;
        const int k0 = kt * BK;
#pragma unroll
        for (int i = 0; i < A_LD; i++) {
            int idx = tid + i * THREADS;
            int r = idx / (BK / 4);
            int c4 = (idx % (BK / 4)) * 4;
            uint32_t s = (uint32_t)__cvta_generic_to_shared(&As[r * LDR + c4]);
            cp16(s, A + (brow + r) * K + k0 + c4);
        }
#pragma unroll
        for (int i = 0; i < B_LD; i++) {
            int idx = tid + i * THREADS;
            int r = idx / (BK / 4);
            int c4 = (idx % (BK / 4)) * 4;
            uint32_t s = (uint32_t)__cvta_generic_to_shared(&Bs[r * LDR + c4]);
            cp16(s, B + (bcol + r) * K + k0 + c4);
        }
        cp_commit();
    };

    float acc[WM_ITER][WN_ITER][4];
#pragma unroll
    for (int i = 0; i < WM_ITER; i++)
#pragma unroll
        for (int j = 0; j < WN_ITER; j++)
#pragma unroll
            for (int t = 0; t < 4; t++) acc[i][j][t] = 0.0f;

    // Prologue: prefetch tiles 0 and 1.
    issue_tile(0);
    if (NK > 1) issue_tile(1);

    for (int kt = 0; kt < NK; kt++) {
        if (kt + 1 < NK)
            asm volatile("cp.async.wait_group 1;" ::: "memory");
        else
            asm volatile("cp.async.wait_group 0;" ::: "memory");
        __syncthreads();

        // Prefetch tile kt+2 into the ring (safe: all warps finished reading
        // that stage during iter kt-1, before this iteration's barrier).
        if (kt + 2 < NK) issue_tile(kt + 2);

        const int st = kt % STAGES;
        const float* As = smem + st * SSZ;
        const float* Bs = As + ASZ;

#pragma unroll
        for (int ks = 0; ks < BK / 8; ks++) {
            uint32_t af[WM_ITER][4];
            uint32_t bf[WN_ITER][2];
#pragma unroll
            for (int i = 0; i < WM_ITER; i++) {
                int r = wm0 + i * 16;
                af[i][0] = as_tf32(As[(r + gid) * LDR + ks * 8 + tig]);
                af[i][1] = as_tf32(As[(r + gid + 8) * LDR + ks * 8 + tig]);
                af[i][2] = as_tf32(As[(r + gid) * LDR + ks * 8 + tig + 4]);
                af[i][3] = as_tf32(As[(r + gid + 8) * LDR + ks * 8 + tig + 4]);
            }
#pragma unroll
            for (int j = 0; j < WN_ITER; j++) {
                int c = wn0 + j * 8;
                bf[j][0] = as_tf32(Bs[(c + gid) * LDR + ks * 8 + tig]);
                bf[j][1] = as_tf32(Bs[(c + gid) * LDR + ks * 8 + tig + 4]);
            }
#pragma unroll
            for (int i = 0; i < WM_ITER; i++)
#pragma unroll
                for (int j = 0; j < WN_ITER; j++) mma_tf32(acc[i][j], af[i], bf[j]);
        }
    }

    // Epilogue: c0,c1 adjacent cols at (gid, 2*tig); c2,c3 at row+8.
#pragma unroll
    for (int i = 0; i < WM_ITER; i++) {
#pragma unroll
        for (int j = 0; j < WN_ITER; j++) {
            long r = brow + wm0 + i * 16 + gid;
            long c = bcol + wn0 + j * 8 + tig * 2;
            *reinterpret_cast<float2*>(C + r * N + c) =
                make_float2(acc[i][j][0], acc[i][j][1]);
            *reinterpret_cast<float2*>(C + (r + 8) * N + c) =
                make_float2(acc[i][j][2], acc[i][j][3]);
        }
    }
}

// One block per batch row: g = (g_raw + bias) * rsqrt(mean(sq)+eps) * scale
__global__ void rmsnorm_kernel(const float* __restrict__ gin,
                               const float* __restrict__ bias,
                               const float* __restrict__ scale,
                               float* __restrict__ gout) {
    const int b = blockIdx.x;
    const int h = threadIdx.x;  // 256 threads
    float v = gin[b * 256 + h] + bias[h];
    float s = v * v;
#pragma unroll
    for (int o = 16; o > 0; o >>= 1) s += __shfl_xor_sync(0xFFFFFFFFu, s, o);
    __shared__ float ws[8];
    if ((h & 31) == 0) ws[h >> 5] = s;
    __syncthreads();
    float tot = 0.0f;
#pragma unroll
    for (int w = 0; w < 8; w++) tot += ws[w];
    float inv = rsqrtf(tot * (1.0f / 256.0f) + 1e-6f);
    gout[b * 256 + h] = v * inv * scale[h];
}

extern "C" void kernel_launch(void* const* d_in, const int* in_sizes, int n_in,
                              void* d_out, int out_size) {
    const float* x         = (const float*)d_in[0];  // (1024, 64, 1024)
    const float* W_tc      = (const float*)d_in[1];  // (32, 1024)
    const float* W_gc      = (const float*)d_in[2];  // (256, 2048)
    const float* b_gc      = (const float*)d_in[3];  // (256,)
    const float* rms_scale = (const float*)d_in[4];  // (256,)
    const float* W_heads   = (const float*)d_in[5];  // (16, 256, 256) -> (4096, 256)
    const float* W_logit   = (const float*)d_in[6];  // (4096, 256)
    float* out = (float*)d_out;                      // (1024, 16, 64, 64)

    float *flat, *graw, *gg, *hr;
    cudaGetSymbolAddress((void**)&flat, g_flat);
    cudaGetSymbolAddress((void**)&graw, g_graw);
    cudaGetSymbolAddress((void**)&gg, g_g);
    cudaGetSymbolAddress((void**)&hr, g_hr);

    constexpr int PAD = 4;
    // Stage A: M=65536, N=32, K=1024. BM=128, BN=32, 3-stage.
    {
        auto k = gemm_tf32_pipe<128, 32, 32, 8, 1, 1, 4, 3>;
        size_t smem = 3 * (size_t)(128 + 32) * (32 + PAD) * sizeof(float);  // 69120
        cudaFuncSetAttribute(k, cudaFuncAttributeMaxDynamicSharedMemorySize, (int)smem);
        k<<<dim3(1, 512), 256, smem>>>(x, W_tc, flat, 65536, 32, 1024);
    }
    // Stage B: M=1024, N=256, K=2048. BM=128, BN=64, 3-stage.
    {
        auto k = gemm_tf32_pipe<128, 64, 32, 2, 4, 4, 2, 3>;
        size_t smem = 3 * (size_t)(128 + 64) * (32 + PAD) * sizeof(float);  // 82944
        cudaFuncSetAttribute(k, cudaFuncAttributeMaxDynamicSharedMemorySize, (int)smem);
        k<<<dim3(4, 8), 256, smem>>>(flat, W_gc, graw, 1024, 256, 2048);
    }
    // RMSNorm (with bias add)
    rmsnorm_kernel<<<1024, 256>>>(graw, b_gc, rms_scale, gg);

    // Stages C/D share the 128x128 config, 3-stage ring (110.6 KB smem).
    {
        auto k = gemm_tf32_pipe<128, 128, 32, 2, 4, 4, 4, 3>;
        size_t smem = 3 * (size_t)(128 + 128) * (32 + PAD) * sizeof(float);  // 110592
        cudaFuncSetAttribute(k, cudaFuncAttributeMaxDynamicSharedMemorySize, (int)smem);
        // Stage C: M=1024, N=4096, K=256.
        k<<<dim3(32, 8), 256, smem>>>(gg, W_heads, hr, 1024, 4096, 256);
        // Stage D: M=16384, N=4096, K=256. Output written directly.
        k<<<dim3(32, 128), 256, smem>>>(hr, W_logit, out, 16384, 4096, 256);
    }
}

// round 7
// speedup vs baseline: 1.4714x; 1.1534x over previous
#include <cuda_runtime.h>
#include <cstdint>

// ---------------------------------------------------------------------------
// Smolgen pipeline on GB300 (sm_103a), round 6: cp.async pipelined TF32
// mma.sync GEMMs with pre-rounded (tf32/RNA) operands so the mainloop has
// zero CVT instructions, and 64x64 warp tiles for stages C/D.
//   A: flat = x @ W_tcR^T          (65536 x 32,  K=1024)  [cvt on A frags only]
//   B: graw = flat @ W_gcR^T       (1024 x 256,  K=2048)
//      rmsnorm -> gg (tf32-rounded)
//   C: hr = gg @ W_headsR^T        (1024 x 4096, K=256)
//   D: out = hr @ W_logitR^T       (16384 x 4096, K=256)
// ---------------------------------------------------------------------------

__device__ float g_flat[1024 * 2048];
__device__ float g_graw[1024 * 256];
__device__ float g_g[1024 * 256];
__device__ float g_hr[1024 * 4096];
__device__ float g_WtcR[32 * 1024];
__device__ float g_WgcR[256 * 2048];
__device__ float g_WheadsR[16 * 256 * 256];
__device__ float g_WlogitR[4096 * 256];

__device__ __forceinline__ float round_tf32(float x) {
    float y;
    asm("cvt.rna.tf32.f32 %0, %1;" : "=f"(y) : "f"(x));
    return y;
}
__device__ __forceinline__ uint32_t as_tf32(float x) {
    return __float_as_uint(round_tf32(x));
}

__device__ __forceinline__ void mma_tf32(float* d, const uint32_t* a, const uint32_t* b) {
    asm volatile(
        "mma.sync.aligned.m16n8k8.row.col.f32.tf32.tf32.f32 "
        "{%0,%1,%2,%3},{%4,%5,%6,%7},{%8,%9},{%0,%1,%2,%3};"
        : "+f"(d[0]), "+f"(d[1]), "+f"(d[2]), "+f"(d[3])
        : "r"(a[0]), "r"(a[1]), "r"(a[2]), "r"(a[3]), "r"(b[0]), "r"(b[1]));
}

__device__ __forceinline__ void cp16(uint32_t saddr, const float* gptr) {
    asm volatile("cp.async.cg.shared.global [%0], [%1], 16;" ::"r"(saddr), "l"(gptr));
}
__device__ __forceinline__ void cp_commit() { asm volatile("cp.async.commit_group;"); }
__device__ __forceinline__ uint32_t smem_u32(const void* p) {
    return (uint32_t)__cvta_generic_to_shared(p);
}

// C[M,N] = A[M,K] @ B[N,K]^T, all row-major fp32. Dims divide tiles exactly.
// CVT_A: apply RNA-tf32 rounding to A fragments (A not pre-rounded).
// B operands must always be pre-rounded tf32 values.
// ROUND_OUT: round outputs to tf32 for the next consumer.
template <int BM, int BN, int BK, int WARPS_M, int WARPS_N, int WM_ITER, int WN_ITER,
          int STAGES, bool CVT_A, bool ROUND_OUT>
__global__ void __launch_bounds__(WARPS_M* WARPS_N * 32, 1)
    gemm_tf32_pipe(const float* __restrict__ A, const float* __restrict__ B,
                   float* __restrict__ C, int M, int N, int K) {
    static_assert(BM == WARPS_M * WM_ITER * 16, "BM mismatch");
    static_assert(BN == WARPS_N * WN_ITER * 8, "BN mismatch");
    constexpr int THREADS = WARPS_M * WARPS_N * 32;
    constexpr int PAD = 4;  // row stride 36 floats -> conflict-free fragment LDS
    constexpr int LDR = BK + PAD;
    constexpr int ASZ = BM * LDR;
    constexpr int BSZ = BN * LDR;
    constexpr int SSZ = ASZ + BSZ;

    extern __shared__ float smem[];

    const int tid = threadIdx.x;
    const int warp = tid >> 5;
    const int lane = tid & 31;
    const int gid = lane >> 2;
    const int tig = lane & 3;
    const int warp_m = warp / WARPS_N;
    const int warp_n = warp % WARPS_N;
    const int wm0 = warp_m * (WM_ITER * 16);
    const int wn0 = warp_n * (WN_ITER * 8);
    const long brow = (long)blockIdx.y * BM;
    const long bcol = (long)blockIdx.x * BN;

    constexpr int A_LD = (BM * BK / 4) / THREADS;
    constexpr int B_LD = (BN * BK / 4) / THREADS;
    static_assert(A_LD * THREADS * 4 == BM * BK, "A load mismatch");
    static_assert(B_LD * THREADS * 4 == BN * BK, "B load mismatch");

    const int NK = K / BK;

    auto issue_tile = [&](int kt) {
        const int st = kt % STAGES;
        float* As = smem + st * SSZ;
        float* Bs = As + ASZ;
        const int k0 = kt * BK;
#pragma unroll
        for (int i = 0; i < A_LD; i++) {
            int idx = tid + i * THREADS;
            int r = idx / (BK / 4);
            int c4 = (idx % (BK / 4)) * 4;
            cp16(smem_u32(&As[r * LDR + c4]), A + (brow + r) * K + k0 + c4);
        }
#pragma unroll
        for (int i = 0; i < B_LD; i++) {
            int idx = tid + i * THREADS;
            int r = idx / (BK / 4);
            int c4 = (idx % (BK / 4)) * 4;
            cp16(smem_u32(&Bs[r * LDR + c4]), B + (bcol + r) * K + k0 + c4);
        }
        cp_commit();
    };

    float acc[WM_ITER][WN_ITER][4];
#pragma unroll
    for (int i = 0; i < WM_ITER; i++)
#pragma unroll
        for (int j = 0; j < WN_ITER; j++)
#pragma unroll
            for (int t = 0; t < 4; t++) acc[i][j][t] = 0.0f;

    issue_tile(0);
    if (NK > 1) issue_tile(1);

    for (int kt = 0; kt < NK; kt++) {
        if (kt + 1 < NK)
            asm volatile("cp.async.wait_group 1;" ::: "memory");
        else
            asm volatile("cp.async.wait_group 0;" ::: "memory");
        __syncthreads();
        if (kt + 2 < NK) issue_tile(kt + 2);

        const int st = kt % STAGES;
        const float* As = smem + st * SSZ;
        const float* Bs = As + ASZ;

#pragma unroll
        for (int ks = 0; ks < BK / 8; ks++) {
            uint32_t af[WM_ITER][4];
            uint32_t bf[WN_ITER][2];
#pragma unroll
            for (int i = 0; i < WM_ITER; i++) {
                int r = wm0 + i * 16;
                if (CVT_A) {
                    af[i][0] = as_tf32(As[(r + gid) * LDR + ks * 8 + tig]);
                    af[i][1] = as_tf32(As[(r + gid + 8) * LDR + ks * 8 + tig]);
                    af[i][2] = as_tf32(As[(r + gid) * LDR + ks * 8 + tig + 4]);
                    af[i][3] = as_tf32(As[(r + gid + 8) * LDR + ks * 8 + tig + 4]);
                } else {
                    af[i][0] = __float_as_uint(As[(r + gid) * LDR + ks * 8 + tig]);
                    af[i][1] = __float_as_uint(As[(r + gid + 8) * LDR + ks * 8 + tig]);
                    af[i][2] = __float_as_uint(As[(r + gid) * LDR + ks * 8 + tig + 4]);
                    af[i][3] = __float_as_uint(As[(r + gid + 8) * LDR + ks * 8 + tig + 4]);
                }
            }
#pragma unroll
            for (int j = 0; j < WN_ITER; j++) {
                int c = wn0 + j * 8;
                bf[j][0] = __float_as_uint(Bs[(c + gid) * LDR + ks * 8 + tig]);
                bf[j][1] = __float_as_uint(Bs[(c + gid) * LDR + ks * 8 + tig + 4]);
            }
#pragma unroll
            for (int i = 0; i < WM_ITER; i++)
#pragma unroll
                for (int j = 0; j < WN_ITER; j++) mma_tf32(acc[i][j], af[i], bf[j]);
        }
    }

    // Epilogue: c0,c1 adjacent cols at (gid, 2*tig); c2,c3 at row+8.
#pragma unroll
    for (int i = 0; i < WM_ITER; i++) {
#pragma unroll
        for (int j = 0; j < WN_ITER; j++) {
            long r = brow + wm0 + i * 16 + gid;
            long c = bcol + wn0 + j * 8 + tig * 2;
            float v0 = acc[i][j][0], v1 = acc[i][j][1];
            float v2 = acc[i][j][2], v3 = acc[i][j][3];
            if (ROUND_OUT) {
                v0 = round_tf32(v0);
                v1 = round_tf32(v1);
                v2 = round_tf32(v2);
                v3 = round_tf32(v3);
            }
            *reinterpret_cast<float2*>(C + r * N + c) = make_float2(v0, v1);
            *reinterpret_cast<float2*>(C + (r + 8) * N + c) = make_float2(v2, v3);
        }
    }
}

// RMSNorm: g = (graw + bias) * rsqrt(mean(sq)+eps) * scale, rounded to tf32.
__global__ void rmsnorm_kernel(const float* __restrict__ gin,
                               const float* __restrict__ bias,
                               const float* __restrict__ scale,
                               float* __restrict__ gout) {
    const int b = blockIdx.x;
    const int h = threadIdx.x;  // 256 threads
    float v = gin[b * 256 + h] + bias[h];
    float s = v * v;
#pragma unroll
    for (int o = 16; o > 0; o >>= 1) s += __shfl_xor_sync(0xFFFFFFFFu, s, o);
    __shared__ float ws[8];
    if ((h & 31) == 0) ws[h >> 5] = s;
    __syncthreads();
    float tot = 0.0f;
#pragma unroll
    for (int w = 0; w < 8; w++) tot += ws[w];
    float inv = rsqrtf(tot * (1.0f / 256.0f) + 1e-6f);
    gout[b * 256 + h] = round_tf32(v * inv * scale[h]);
}

// Round a weight tensor to tf32 (RNA). n multiple of 4, float4 vectorized.
__global__ void round_weights_kernel(const float* __restrict__ src,
                                     float* __restrict__ dst, int n4) {
    int i = blockIdx.x * blockDim.x + threadIdx.x;
    if (i < n4) {
        float4 v = reinterpret_cast<const float4*>(src)[i];
        v.x = round_tf32(v.x);
        v.y = round_tf32(v.y);
        v.z = round_tf32(v.z);
        v.w = round_tf32(v.w);
        reinterpret_cast<float4*>(dst)[i] = v;
    }
}

extern "C" void kernel_launch(void* const* d_in, const int* in_sizes, int n_in,
                              void* d_out, int out_size) {
    const float* x         = (const float*)d_in[0];  // (1024, 64, 1024)
    const float* W_tc      = (const float*)d_in[1];  // (32, 1024)
    const float* W_gc      = (const float*)d_in[2];  // (256, 2048)
    const float* b_gc      = (const float*)d_in[3];  // (256,)
    const float* rms_scale = (const float*)d_in[4];  // (256,)
    const float* W_heads   = (const float*)d_in[5];  // (16, 256, 256)
    const float* W_logit   = (const float*)d_in[6];  // (4096, 256)
    float* out = (float*)d_out;                      // (1024, 16, 64, 64)

    float *flat, *graw, *gg, *hr, *wtcR, *wgcR, *whR, *wlR;
    cudaGetSymbolAddress((void**)&flat, g_flat);
    cudaGetSymbolAddress((void**)&graw, g_graw);
    cudaGetSymbolAddress((void**)&gg, g_g);
    cudaGetSymbolAddress((void**)&hr, g_hr);
    cudaGetSymbolAddress((void**)&wtcR, g_WtcR);
    cudaGetSymbolAddress((void**)&wgcR, g_WgcR);
    cudaGetSymbolAddress((void**)&whR, g_WheadsR);
    cudaGetSymbolAddress((void**)&wlR, g_WlogitR);

    // Pre-round all weights to tf32 (RNA) once per launch.
    auto rw = [&](const float* s, float* d, int n) {
        int n4 = n / 4;
        round_weights_kernel<<<(n4 + 255) / 256, 256>>>(s, d, n4);
    };
    rw(W_tc, wtcR, 32 * 1024);
    rw(W_gc, wgcR, 256 * 2048);
    rw(W_heads, whR, 16 * 256 * 256);
    rw(W_logit, wlR, 4096 * 256);

    constexpr int PAD = 4;
    // Stage A: M=65536, N=32, K=1024. cvt on A frags (x is raw fp32);
    // output rounded for stage B.
    {
        auto k = gemm_tf32_pipe<128, 32, 32, 8, 1, 1, 4, 3, true, true>;
        size_t smem = 3 * (size_t)(128 + 32) * (32 + PAD) * sizeof(float);
        cudaFuncSetAttribute(k, cudaFuncAttributeMaxDynamicSharedMemorySize, (int)smem);
        k<<<dim3(1, 512), 256, smem>>>(x, wtcR, flat, 65536, 32, 1024);
    }
    // Stage B: M=1024, N=256, K=2048. No cvt; output left fp32 (rms rounds).
    {
        auto k = gemm_tf32_pipe<128, 64, 32, 2, 4, 4, 2, 3, false, false>;
        size_t smem = 3 * (size_t)(128 + 64) * (32 + PAD) * sizeof(float);
        cudaFuncSetAttribute(k, cudaFuncAttributeMaxDynamicSharedMemorySize, (int)smem);
        k<<<dim3(4, 8), 256, smem>>>(flat, wgcR, graw, 1024, 256, 2048);
    }
    rmsnorm_kernel<<<1024, 256>>>(graw, b_gc, rms_scale, gg);

    // Stages C/D: BM=128, BN=256, 64x64 warp tiles, no cvt. 165.9 KB smem.
    {
        size_t smem = 3 * (size_t)(128 + 256) * (32 + PAD) * sizeof(float);
        // Stage C: output rounded for stage D.
        auto kc = gemm_tf32_pipe<128, 256, 32, 2, 4, 4, 8, 3, false, true>;
        cudaFuncSetAttribute(kc, cudaFuncAttributeMaxDynamicSharedMemorySize, (int)smem);
        kc<<<dim3(16, 8), 256, smem>>>(gg, whR, hr, 1024, 4096, 256);
        // Stage D: final output, no rounding.
        auto kd = gemm_tf32_pipe<128, 256, 32, 2, 4, 4, 8, 3, false, false>;
        cudaFuncSetAttribute(kd, cudaFuncAttributeMaxDynamicSharedMemorySize, (int)smem);
        kd<<<dim3(16, 128), 256, smem>>>(hr, wlR, out, 16384, 4096, 256);
    }
}

// round 8
// speedup vs baseline: 1.4833x; 1.0080x over previous
#include <cuda_runtime.h>
#include <cstdint>

// ---------------------------------------------------------------------------
// Smolgen pipeline on GB300 (sm_103a), round 8:
//   A: flat = x @ W_tcR^T          (65536 x 32,  K=1024)  scalar-LDS pipeline
//   B: graw = flat @ W_gcR^T       (1024 x 256,  K=2048)  scalar-LDS pipeline
//      rmsnorm -> gg (tf32-rounded)
//   C: hr = gg @ W_headsR^T        (1024 x 4096, K=256)   LDSM kernel
//   D: out = hr @ W_logitR^T       (16384 x 4096, K=256)  LDSM kernel
// New C/D kernel: ldmatrix.x4 fragment loads (8 loads per 32 MMAs per ks),
// BK=64, 2-stage cp.async ring, 128x256 CTA tile, 64x64 warp tiles.
// All GEMM operands pre-rounded to tf32 (RNA) -> zero CVT in mainloops,
// numerics bit-identical to previous rounds (rel_err 5.886e-4).
// ---------------------------------------------------------------------------

__device__ float g_flat[1024 * 2048];
__device__ float g_graw[1024 * 256];
__device__ float g_g[1024 * 256];
__device__ float g_hr[1024 * 4096];
__device__ float g_WtcR[32 * 1024];
__device__ float g_WgcR[256 * 2048];
__device__ float g_WheadsR[16 * 256 * 256];
__device__ float g_WlogitR[4096 * 256];

__device__ __forceinline__ float round_tf32(float x) {
    float y;
    asm("cvt.rna.tf32.f32 %0, %1;" : "=f"(y) : "f"(x));
    return y;
}
__device__ __forceinline__ uint32_t as_tf32(float x) {
    return __float_as_uint(round_tf32(x));
}

__device__ __forceinline__ void mma_tf32(float* d, const uint32_t* a, const uint32_t* b) {
    asm volatile(
        "mma.sync.aligned.m16n8k8.row.col.f32.tf32.tf32.f32 "
        "{%0,%1,%2,%3},{%4,%5,%6,%7},{%8,%9},{%0,%1,%2,%3};"
        : "+f"(d[0]), "+f"(d[1]), "+f"(d[2]), "+f"(d[3])
        : "r"(a[0]), "r"(a[1]), "r"(a[2]), "r"(a[3]), "r"(b[0]), "r"(b[1]));
}

__device__ __forceinline__ void ldsm_x4(uint32_t* r, uint32_t addr) {
    asm volatile(
        "ldmatrix.sync.aligned.m8n8.x4.shared.b16 {%0,%1,%2,%3}, [%4];"
        : "=r"(r[0]), "=r"(r[1]), "=r"(r[2]), "=r"(r[3])
        : "r"(addr));
}

__device__ __forceinline__ void cp16(uint32_t saddr, const float* gptr) {
    asm volatile("cp.async.cg.shared.global [%0], [%1], 16;" ::"r"(saddr), "l"(gptr));
}
__device__ __forceinline__ void cp_commit() { asm volatile("cp.async.commit_group;"); }
__device__ __forceinline__ uint32_t smem_u32(const void* p) {
    return (uint32_t)__cvta_generic_to_shared(p);
}

// ======================= LDSM tf32 GEMM (stages C, D) ========================
// C[M,N] = A[M,K] @ B[N,K]^T, row-major fp32, operands pre-rounded to tf32.
// BM=128, BN=256, BK=64, 8 warps (2x4 grid of 64x64 warp tiles), 2 stages.
// M%128==0, N%256==0, K%64==0.
template <bool ROUND_OUT>
__global__ void __launch_bounds__(256, 1)
    gemm_ldsm(const float* __restrict__ A, const float* __restrict__ B,
              float* __restrict__ C, int M, int N, int K) {
    constexpr int BM = 128, BN = 256, BK = 64;
    constexpr int LDR = BK + 4;              // 68 floats: rows offset 4 banks
    constexpr int ASZB = BM * LDR * 4;       // bytes
    constexpr int BSZB = BN * LDR * 4;
    constexpr int SSZB = ASZB + BSZB;        // 104,448 B per stage

    extern __shared__ float smem[];
    const uint32_t sbase = smem_u32(smem);

    const int tid = threadIdx.x;
    const int warp = tid >> 5;
    const int lane = tid & 31;
    const int gid = lane >> 2;
    const int tig = lane & 3;
    const int wm0 = (warp >> 2) * 64;   // warp_m in {0,1}
    const int wn0 = (warp & 3) * 64;    // warp_n in {0..3}
    const long brow = (long)blockIdx.y * BM;
    const long bcol = (long)blockIdx.x * BN;
    const int NK = K / BK;

    // LDSM per-lane address offsets.
    // A x4 submatrices: {rows+0,k+0} {rows+8,k+0} {rows+0,k+4} {rows+8,k+4}
    const int rowOffA = (lane & 7) + ((lane >> 3) & 1) * 8;
    const int colOffA = (lane >> 4) * 4;
    // B x4 submatrices: {j,k+0} {j,k+4} {j+1,k+0} {j+1,k+4}
    const int rowOffB = (lane & 7) + (lane >> 4) * 8;
    const int colOffB = ((lane >> 3) & 1) * 4;
    const uint32_t aLane = 4u * ((wm0 + rowOffA) * LDR + colOffA);
    const uint32_t bLane = 4u * ((wn0 + rowOffB) * LDR + colOffB);

    auto issue_tile = [&](int kt) {
        const uint32_t st = sbase + (uint32_t)(kt & 1) * SSZB;
        const int k0 = kt * BK;
        // A: 128 rows x 16 chunks = 2048, 8 per thread.
#pragma unroll
        for (int i = 0; i < 8; i++) {
            int idx = tid + i * 256;
            int r = idx >> 4, c = idx & 15;
            cp16(st + 4u * (r * LDR + c * 4), A + (brow + r) * K + k0 + c * 4);
        }
        // B: 256 rows x 16 chunks = 4096, 16 per thread.
#pragma unroll
        for (int i = 0; i < 16; i++) {
            int idx = tid + i * 256;
            int r = idx >> 4, c = idx & 15;
            cp16(st + ASZB + 4u * (r * LDR + c * 4),
                 B + (bcol + r) * K + k0 + c * 4);
        }
        cp_commit();
    };

    float acc[4][8][4];
#pragma unroll
    for (int i = 0; i < 4; i++)
#pragma unroll
        for (int j = 0; j < 8; j++)
#pragma unroll
            for (int t = 0; t < 4; t++) acc[i][j][t] = 0.0f;

    issue_tile(0);
    asm volatile("cp.async.wait_group 0;" ::: "memory");
    __syncthreads();

    for (int kt = 0; kt < NK; kt++) {
        if (kt + 1 < NK) issue_tile(kt + 1);

        const uint32_t st = sbase + (uint32_t)(kt & 1) * SSZB;
        const uint32_t aBase = st + aLane;
        const uint32_t bBase = st + ASZB + bLane;

#pragma unroll
        for (int ks = 0; ks < BK / 8; ks++) {
            uint32_t af[4][4];
            uint32_t bq[4][4];  // bq[jj] = {b[2jj][0], b[2jj][1], b[2jj+1][0], b[2jj+1][1]}
#pragma unroll
            for (int i = 0; i < 4; i++)
                ldsm_x4(af[i], aBase + 4u * (i * 16 * LDR) + ks * 32u);
#pragma unroll
            for (int jj = 0; jj < 4; jj++)
                ldsm_x4(bq[jj], bBase + 4u * (jj * 16 * LDR) + ks * 32u);
#pragma unroll
            for (int i = 0; i < 4; i++)
#pragma unroll
                for (int jj = 0; jj < 4; jj++) {
                    mma_tf32(acc[i][2 * jj], af[i], &bq[jj][0]);
                    mma_tf32(acc[i][2 * jj + 1], af[i], &bq[jj][2]);
                }
        }

        if (kt + 1 < NK) asm volatile("cp.async.wait_group 0;" ::: "memory");
        __syncthreads();
    }

    // Epilogue: acc[i][j] -> rows (wm0+i*16+gid, +8), cols (wn0+j*8+2*tig, +1)
#pragma unroll
    for (int i = 0; i < 4; i++) {
#pragma unroll
        for (int j = 0; j < 8; j++) {
            long r = brow + wm0 + i * 16 + gid;
            long c = bcol + wn0 + j * 8 + tig * 2;
            float v0 = acc[i][j][0], v1 = acc[i][j][1];
            float v2 = acc[i][j][2], v3 = acc[i][j][3];
            if (ROUND_OUT) {
                v0 = round_tf32(v0);
                v1 = round_tf32(v1);
                v2 = round_tf32(v2);
                v3 = round_tf32(v3);
            }
            *reinterpret_cast<float2*>(C + r * N + c) = make_float2(v0, v1);
            *reinterpret_cast<float2*>(C + (r + 8) * N + c) = make_float2(v2, v3);
        }
    }
}

// ================= scalar-LDS pipelined GEMM (stages A, B) ===================
template <int BM, int BN, int BK, int WARPS_M, int WARPS_N, int WM_ITER, int WN_ITER,
          int STAGES, bool CVT_A, bool ROUND_OUT>
__global__ void __launch_bounds__(WARPS_M* WARPS_N * 32, 1)
    gemm_tf32_pipe(const float* __restrict__ A, const float* __restrict__ B,
                   float* __restrict__ C, int M, int N, int K) {
    constexpr int THREADS = WARPS_M * WARPS_N * 32;
    constexpr int PAD = 4;
    constexpr int LDR = BK + PAD;
    constexpr int ASZ = BM * LDR;
    constexpr int BSZ = BN * LDR;
    constexpr int SSZ = ASZ + BSZ;

    extern __shared__ float smem[];

    const int tid = threadIdx.x;
    const int warp = tid >> 5;
    const int lane = tid & 31;
    const int gid = lane >> 2;
    const int tig = lane & 3;
    const int warp_m = warp / WARPS_N;
    const int warp_n = warp % WARPS_N;
    const int wm0 = warp_m * (WM_ITER * 16);
    const int wn0 = warp_n * (WN_ITER * 8);
    const long brow = (long)blockIdx.y * BM;
    const long bcol = (long)blockIdx.x * BN;

    constexpr int A_LD = (BM * BK / 4) / THREADS;
    constexpr int B_LD = (BN * BK / 4) / THREADS;

    const int NK = K / BK;

    auto issue_tile = [&](int kt) {
        const int st = kt % STAGES;
        float* As = smem + st * SSZ;
        float* Bs = As + ASZ;
        const int k0 = kt * BK;
#pragma unroll
        for (int i = 0; i < A_LD; i++) {
            int idx = tid + i * THREADS;
            int r = idx / (BK / 4);
            int c4 = (idx % (BK / 4)) * 4;
            cp16(smem_u32(&As[r * LDR + c4]), A + (brow + r) * K + k0 + c4);
        }
#pragma unroll
        for (int i = 0; i < B_LD; i++) {
            int idx = tid + i * THREADS;
            int r = idx / (BK / 4);
            int c4 = (idx % (BK / 4)) * 4;
            cp16(smem_u32(&Bs[r * LDR + c4]), B + (bcol + r) * K + k0 + c4);
        }
        cp_commit();
    };

    float acc[WM_ITER][WN_ITER][4];
#pragma unroll
    for (int i = 0; i < WM_ITER; i++)
#pragma unroll
        for (int j = 0; j < WN_ITER; j++)
#pragma unroll
            for (int t = 0; t < 4; t++) acc[i][j][t] = 0.0f;

    issue_tile(0);
    if (NK > 1) issue_tile(1);

    for (int kt = 0; kt < NK; kt++) {
        if (kt + 1 < NK)
            asm volatile("cp.async.wait_group 1;" ::: "memory");
        else
            asm volatile("cp.async.wait_group 0;" ::: "memory");
        __syncthreads();
        if (kt + 2 < NK) issue_tile(kt + 2);

        const int st = kt % STAGES;
        const float* As = smem + st * SSZ;
        const float* Bs = As + ASZ;

#pragma unroll
        for (int ks = 0; ks < BK / 8; ks++) {
            uint32_t af[WM_ITER][4];
            uint32_t bf[WN_ITER][2];
#pragma unroll
            for (int i = 0; i < WM_ITER; i++) {
                int r = wm0 + i * 16;
                if (CVT_A) {
                    af[i][0] = as_tf32(As[(r + gid) * LDR + ks * 8 + tig]);
                    af[i][1] = as_tf32(As[(r + gid + 8) * LDR + ks * 8 + tig]);
                    af[i][2] = as_tf32(As[(r + gid) * LDR + ks * 8 + tig + 4]);
                    af[i][3] = as_tf32(As[(r + gid + 8) * LDR + ks * 8 + tig + 4]);
                } else {
                    af[i][0] = __float_as_uint(As[(r + gid) * LDR + ks * 8 + tig]);
                    af[i][1] = __float_as_uint(As[(r + gid + 8) * LDR + ks * 8 + tig]);
                    af[i][2] = __float_as_uint(As[(r + gid) * LDR + ks * 8 + tig + 4]);
                    af[i][3] = __float_as_uint(As[(r + gid + 8) * LDR + ks * 8 + tig + 4]);
                }
            }
#pragma unroll
            for (int j = 0; j < WN_ITER; j++) {
                int c = wn0 + j * 8;
                bf[j][0] = __float_as_uint(Bs[(c + gid) * LDR + ks * 8 + tig]);
                bf[j][1] = __float_as_uint(Bs[(c + gid) * LDR + ks * 8 + tig + 4]);
            }
#pragma unroll
            for (int i = 0; i < WM_ITER; i++)
#pragma unroll
                for (int j = 0; j < WN_ITER; j++) mma_tf32(acc[i][j], af[i], bf[j]);
        }
    }

#pragma unroll
    for (int i = 0; i < WM_ITER; i++) {
#pragma unroll
        for (int j = 0; j < WN_ITER; j++) {
            long r = brow + wm0 + i * 16 + gid;
            long c = bcol + wn0 + j * 8 + tig * 2;
            float v0 = acc[i][j][0], v1 = acc[i][j][1];
            float v2 = acc[i][j][2], v3 = acc[i][j][3];
            if (ROUND_OUT) {
                v0 = round_tf32(v0);
                v1 = round_tf32(v1);
                v2 = round_tf32(v2);
                v3 = round_tf32(v3);
            }
            *reinterpret_cast<float2*>(C + r * N + c) = make_float2(v0, v1);
            *reinterpret_cast<float2*>(C + (r + 8) * N + c) = make_float2(v2, v3);
        }
    }
}

// RMSNorm: g = (graw + bias) * rsqrt(mean(sq)+eps) * scale, rounded to tf32.
__global__ void rmsnorm_kernel(const float* __restrict__ gin,
                               const float* __restrict__ bias,
                               const float* __restrict__ scale,
                               float* __restrict__ gout) {
    const int b = blockIdx.x;
    const int h = threadIdx.x;  // 256 threads
    float v = gin[b * 256 + h] + bias[h];
    float s = v * v;
#pragma unroll
    for (int o = 16; o > 0; o >>= 1) s += __shfl_xor_sync(0xFFFFFFFFu, s, o);
    __shared__ float ws[8];
    if ((h & 31) == 0) ws[h >> 5] = s;
    __syncthreads();
    float tot = 0.0f;
#pragma unroll
    for (int w = 0; w < 8; w++) tot += ws[w];
    float inv = rsqrtf(tot * (1.0f / 256.0f) + 1e-6f);
    gout[b * 256 + h] = round_tf32(v * inv * scale[h]);
}

// Round a weight tensor to tf32 (RNA). n multiple of 4, float4 vectorized.
__global__ void round_weights_kernel(const float* __restrict__ src,
                                     float* __restrict__ dst, int n4) {
    int i = blockIdx.x * blockDim.x + threadIdx.x;
    if (i < n4) {
        float4 v = reinterpret_cast<const float4*>(src)[i];
        v.x = round_tf32(v.x);
        v.y = round_tf32(v.y);
        v.z = round_tf32(v.z);
        v.w = round_tf32(v.w);
        reinterpret_cast<float4*>(dst)[i] = v;
    }
}

extern "C" void kernel_launch(void* const* d_in, const int* in_sizes, int n_in,
                              void* d_out, int out_size) {
    const float* x         = (const float*)d_in[0];  // (1024, 64, 1024)
    const float* W_tc      = (const float*)d_in[1];  // (32, 1024)
    const float* W_gc      = (const float*)d_in[2];  // (256, 2048)
    const float* b_gc      = (const float*)d_in[3];  // (256,)
    const float* rms_scale = (const float*)d_in[4];  // (256,)
    const float* W_heads   = (const float*)d_in[5];  // (16, 256, 256)
    const float* W_logit   = (const float*)d_in[6];  // (4096, 256)
    float* out = (float*)d_out;                      // (1024, 16, 64, 64)

    float *flat, *graw, *gg, *hr, *wtcR, *wgcR, *whR, *wlR;
    cudaGetSymbolAddress((void**)&flat, g_flat);
    cudaGetSymbolAddress((void**)&graw, g_graw);
    cudaGetSymbolAddress((void**)&gg, g_g);
    cudaGetSymbolAddress((void**)&hr, g_hr);
    cudaGetSymbolAddress((void**)&wtcR, g_WtcR);
    cudaGetSymbolAddress((void**)&wgcR, g_WgcR);
    cudaGetSymbolAddress((void**)&whR, g_WheadsR);
    cudaGetSymbolAddress((void**)&wlR, g_WlogitR);

    // Pre-round all weights to tf32 (RNA) once per launch.
    auto rw = [&](const float* s, float* d, int n) {
        int n4 = n / 4;
        round_weights_kernel<<<(n4 + 255) / 256, 256>>>(s, d, n4);
    };
    rw(W_tc, wtcR, 32 * 1024);
    rw(W_gc, wgcR, 256 * 2048);
    rw(W_heads, whR, 16 * 256 * 256);
    rw(W_logit, wlR, 4096 * 256);

    constexpr int PAD = 4;
    // Stage A: M=65536, N=32, K=1024. cvt on A frags; output rounded.
    {
        auto k = gemm_tf32_pipe<128, 32, 32, 8, 1, 1, 4, 3, true, true>;
        size_t smem = 3 * (size_t)(128 + 32) * (32 + PAD) * sizeof(float);
        cudaFuncSetAttribute(k, cudaFuncAttributeMaxDynamicSharedMemorySize, (int)smem);
        k<<<dim3(1, 512), 256, smem>>>(x, wtcR, flat, 65536, 32, 1024);
    }
    // Stage B: M=1024, N=256, K=2048. Output left fp32 (rmsnorm rounds).
    {
        auto k = gemm_tf32_pipe<128, 64, 32, 2, 4, 4, 2, 3, false, false>;
        size_t smem = 3 * (size_t)(128 + 64) * (32 + PAD) * sizeof(float);
        cudaFuncSetAttribute(k, cudaFuncAttributeMaxDynamicSharedMemorySize, (int)smem);
        k<<<dim3(4, 8), 256, smem>>>(flat, wgcR, graw, 1024, 256, 2048);
    }
    rmsnorm_kernel<<<1024, 256>>>(graw, b_gc, rms_scale, gg);

    // Stages C/D: LDSM kernel, BK=64, 2 stages, 208,896 B smem.
    {
        size_t smem = 2 * (size_t)(128 + 256) * (64 + 4) * sizeof(float);
        auto kc = gemm_ldsm<true>;
        auto kd = gemm_ldsm<false>;
        cudaFuncSetAttribute(kc, cudaFuncAttributeMaxDynamicSharedMemorySize, (int)smem);
        cudaFuncSetAttribute(kd, cudaFuncAttributeMaxDynamicSharedMemorySize, (int)smem);
        // C: M=1024, N=4096, K=256 -> grid (16, 8) = 128 CTAs.
        kc<<<dim3(16, 8), 256, smem>>>(gg, whR, hr, 1024, 4096, 256);
        // D: M=16384, N=4096, K=256 -> grid (16, 128) = 2048 CTAs.
        kd<<<dim3(16, 128), 256, smem>>>(hr, wlR, out, 16384, 4096, 256);
    }
}